// round 5
// baseline (speedup 1.0000x reference)
#include <cuda_runtime.h>

#define NV 5
#define NS 4
#define CC 32
#define HH 128
#define WW 160
#define DDEP 48
#define HWSZ (HH*WW)          // 20480
#define DHWSZ (DDEP*HWSZ)     // 983040

// conv tiling
#define HT 4
#define HS 6
#define DT 8
#define DS 10
#define WP 168
#define CONV_THREADS 160
#define CSPLIT 2
#define CPB (CC/CSPLIT)

// k_var tiling
#define TPX 16                // pixels per block (one 16-wide strip of a row)
#define VAR_THREADS 128       // 16 px x 8 channel-groups

// ---------------- scratch ----------------------------------------------------
__device__ float g_rot[NS][9];
__device__ float g_trans[NS][3];
__device__ float g_feaT[NV*HWSZ*CC];            // (view, h, w, c)
__device__ float g_var[(size_t)CC*DHWSZ];       // planar (c, d,h,w)
__device__ float g_cost[DHWSZ];
__device__ float g_cost2[DHWSZ];

// ---------------- packed f32x2 helpers --------------------------------------
__device__ __forceinline__ unsigned long long pk2(float lo, float hi) {
    unsigned long long p;
    asm("mov.b64 %0, {%1, %2};" : "=l"(p) : "f"(lo), "f"(hi));
    return p;
}
__device__ __forceinline__ unsigned long long fma2(unsigned long long a,
                                                   unsigned long long b,
                                                   unsigned long long c) {
    unsigned long long d;
    asm("fma.rn.f32x2 %0, %1, %2, %3;" : "=l"(d) : "l"(a), "l"(b), "l"(c));
    return d;
}
__device__ __forceinline__ void upk2(unsigned long long p, float& lo, float& hi) {
    asm("mov.b64 {%0, %1}, %2;" : "=f"(lo), "=f"(hi) : "l"(p));
}

// ---------------- kernel 0: projection setup (1 thread) ---------------------
__global__ void k_setup(const float* __restrict__ pm) {
    if (threadIdx.x != 0 || blockIdx.x != 0) return;
    double fused[NV][16];
    for (int n = 0; n < NV; n++) {
        const float* p0 = pm + n * 32;
        const float* p1 = p0 + 16;
        for (int i = 0; i < 16; i++) fused[n][i] = (double)p0[i];
        for (int i = 0; i < 3; i++)
            for (int j = 0; j < 4; j++) {
                double s = 0.0;
                for (int k = 0; k < 3; k++) s += (double)p1[i*4+k] * (double)p0[k*4+j];
                fused[n][i*4+j] = s;
            }
    }
    double a[4][8];
    for (int i = 0; i < 4; i++)
        for (int j = 0; j < 4; j++) {
            a[i][j]   = fused[0][i*4+j];
            a[i][j+4] = (i == j) ? 1.0 : 0.0;
        }
    for (int col = 0; col < 4; col++) {
        int piv = col;
        for (int r = col + 1; r < 4; r++)
            if (fabs(a[r][col]) > fabs(a[piv][col])) piv = r;
        if (piv != col)
            for (int j = 0; j < 8; j++) { double t = a[col][j]; a[col][j] = a[piv][j]; a[piv][j] = t; }
        double d = a[col][col];
        for (int j = 0; j < 8; j++) a[col][j] /= d;
        for (int r = 0; r < 4; r++) {
            if (r == col) continue;
            double f = a[r][col];
            for (int j = 0; j < 8; j++) a[r][j] -= f * a[col][j];
        }
    }
    double inv[16];
    for (int i = 0; i < 4; i++)
        for (int j = 0; j < 4; j++) inv[i*4+j] = a[i][j+4];

    for (int v = 1; v < NV; v++) {
        double P[16];
        for (int i = 0; i < 4; i++)
            for (int j = 0; j < 4; j++) {
                double s = 0.0;
                for (int k = 0; k < 4; k++) s += fused[v][i*4+k] * inv[k*4+j];
                P[i*4+j] = s;
            }
        for (int i = 0; i < 3; i++)
            for (int j = 0; j < 3; j++) g_rot[v-1][i*3+j] = (float)P[i*4+j];
        for (int i = 0; i < 3; i++) g_trans[v-1][i] = (float)P[i*4+3];
    }
}

// ---------------- kernel 1: transpose features (N,C,H,W) -> (N,HW,C) --------
__global__ void k_transpose(const float* __restrict__ f) {
    __shared__ float tile[32][33];
    int n  = blockIdx.z;
    int p0 = blockIdx.x * 32;
    int tx = threadIdx.x, ty = threadIdx.y;
    tile[ty][tx] = f[((size_t)(n*CC + ty))*HWSZ + p0 + tx];
    __syncthreads();
    g_feaT[((size_t)(n*HWSZ + p0 + ty))*CC + tx] = tile[tx][ty];
}

// ---------------- kernel 2: warp + variance, depth-loop with corner cache ---
// Block: 16 pixels (one 16-wide strip of an h-row) x 48 depths.
// Thread (px = tid>>3, cg = tid&7) owns 4 channels of one pixel; bilinear
// corner float4s live in registers across the depth loop and are reloaded
// only when the integer source index changes (rare: px drifts sub-pixel/d).
__global__ void __launch_bounds__(VAR_THREADS, 4) k_var(const float* __restrict__ dv_g) {
    __shared__ int4   s_id[TPX][NS];
    __shared__ float4 s_wt[TPX][NS];
    __shared__ float  s_var[2][TPX][36];
    __shared__ float  s_dv[DDEP];

    const int tid = threadIdx.x;
    const int px  = tid >> 3;         // 0..15  (pixel within tile)
    const int cg  = tid & 7;          // 0..7   (channel group, 4 ch)
    const int v0  = cg & 3;           // view handled in phase1

    const int tile = blockIdx.x;      // 0..1279
    const int h    = tile / (WW/TPX);
    const int w0   = (tile % (WW/TPX)) * TPX;
    const int hwb  = h*WW + w0;

    if (tid < DDEP) s_dv[tid] = dv_g[tid];

    // per-thread (pixel, v0) projection constants
    const float fx = (float)(w0 + px), fy = (float)h;
    const float rx = g_rot[v0][0]*fx + g_rot[v0][1]*fy + g_rot[v0][2];
    const float ry = g_rot[v0][3]*fx + g_rot[v0][4]*fy + g_rot[v0][5];
    const float rz = g_rot[v0][6]*fx + g_rot[v0][7]*fy + g_rot[v0][8];
    const float t0 = g_trans[v0][0], t1 = g_trans[v0][1], t2 = g_trans[v0][2];

    // reference features for (pixel, cg): constant across depth
    const float4* fT = (const float4*)g_feaT;
    const float4 ref = fT[(size_t)(hwb + px)*8 + cg];

    // corner caches
    float4 C[NS][4];
    int4   P[NS];
    #pragma unroll
    for (int v = 0; v < NS; v++) { P[v].x = -1; P[v].y = -1; P[v].z = -1; P[v].w = -1; }

    const float invN = 1.0f / (float)NV;
    const int   c0   = tid >> 4;      // 0..7 (for planar write)
    const int   wpx  = tid & 15;

    __syncthreads();                  // s_dv visible

    #pragma unroll 1
    for (int d = 0; d < DDEP; d++) {
        // ---- phase1: descriptor for (pixel px, view v0) ----
        {
            float depth = s_dv[d];
            float X = rx*depth + t0;
            float Y = ry*depth + t1;
            float Z = rz*depth + t2;
            float pxx = X / Z;
            float pyy = Y / Z;
            float x0 = floorf(pxx), y0 = floorf(pyy);
            float x1 = x0 + 1.0f,   y1 = y0 + 1.0f;
            float wx1 = pxx - x0, wx0 = 1.0f - wx1;
            float wy1 = pyy - y0, wy0 = 1.0f - wy1;
            bool vx0 = (x0 >= 0.0f) && (x0 <= (float)(WW-1));
            bool vx1 = (x1 >= 0.0f) && (x1 <= (float)(WW-1));
            bool vy0 = (y0 >= 0.0f) && (y0 <= (float)(HH-1));
            bool vy1 = (y1 >= 0.0f) && (y1 <= (float)(HH-1));
            int cx0 = (int)fminf(fmaxf(x0, 0.0f), (float)(WW-1));
            int cx1 = (int)fminf(fmaxf(x1, 0.0f), (float)(WW-1));
            int cy0 = (int)fminf(fmaxf(y0, 0.0f), (float)(HH-1));
            int cy1 = (int)fminf(fmaxf(y1, 0.0f), (float)(HH-1));
            int4 id;
            id.x = cy0*WW + cx0;
            id.y = cy0*WW + cx1;
            id.z = cy1*WW + cx0;
            id.w = cy1*WW + cx1;
            float4 wt;
            wt.x = wx0*wy0 * ((vx0 && vy0) ? 1.0f : 0.0f);
            wt.y = wx1*wy0 * ((vx1 && vy0) ? 1.0f : 0.0f);
            wt.z = wx0*wy1 * ((vx0 && vy1) ? 1.0f : 0.0f);
            wt.w = wx1*wy1 * ((vx1 && vy1) ? 1.0f : 0.0f);
            s_id[px][v0] = id;   // cg and cg+4 write identical values
            s_wt[px][v0] = wt;
        }
        __syncwarp();             // descriptors are warp-local (4 px per warp)

        // ---- phase2: gather with register-cached corners ----
        float sx = ref.x, sy = ref.y, sz = ref.z, sw = ref.w;
        float qx = ref.x*ref.x, qy = ref.y*ref.y, qz = ref.z*ref.z, qw = ref.w*ref.w;
        #pragma unroll
        for (int v = 0; v < NS; v++) {
            int4   id = s_id[px][v];
            float4 wt = s_wt[px][v];
            const float4* fv = fT + (size_t)(v+1)*HWSZ*8;
            if (id.x != P[v].x) { C[v][0] = fv[(size_t)id.x*8 + cg]; P[v].x = id.x; }
            if (id.y != P[v].y) { C[v][1] = fv[(size_t)id.y*8 + cg]; P[v].y = id.y; }
            if (id.z != P[v].z) { C[v][2] = fv[(size_t)id.z*8 + cg]; P[v].z = id.z; }
            if (id.w != P[v].w) { C[v][3] = fv[(size_t)id.w*8 + cg]; P[v].w = id.w; }
            float vx = wt.x*C[v][0].x + wt.y*C[v][1].x + wt.z*C[v][2].x + wt.w*C[v][3].x;
            float vy = wt.x*C[v][0].y + wt.y*C[v][1].y + wt.z*C[v][2].y + wt.w*C[v][3].y;
            float vz = wt.x*C[v][0].z + wt.y*C[v][1].z + wt.z*C[v][2].z + wt.w*C[v][3].z;
            float vw = wt.x*C[v][0].w + wt.y*C[v][1].w + wt.z*C[v][2].w + wt.w*C[v][3].w;
            sx += vx; sy += vy; sz += vz; sw += vw;
            qx += vx*vx; qy += vy*vy; qz += vz*vz; qw += vw*vw;
        }
        float mx = sx*invN, my = sy*invN, mz = sz*invN, mw = sw*invN;
        float4 vr;
        vr.x = qx*invN - mx*mx;
        vr.y = qy*invN - my*my;
        vr.z = qz*invN - mz*mz;
        vr.w = qw*invN - mw*mw;
        *(float4*)&s_var[d & 1][px][cg*4] = vr;

        __syncthreads();          // stage complete; also protects buffer reuse

        // ---- planar write: g_var[c][d][hwb + wpx], 16-px contiguous ----
        const size_t dbase = (size_t)d*HWSZ + hwb + wpx;
        #pragma unroll
        for (int j = 0; j < 4; j++) {
            int c = c0 + j*8;
            g_var[(size_t)c*DHWSZ + dbase] = s_var[d & 1][wpx][c];
        }
    }
}

// ---------------- kernel 3: 3x3x3 conv, 16 channels per block (z-split) -----
__global__ void __launch_bounds__(CONV_THREADS) k_conv(const float* __restrict__ wgt) {
    __shared__ float slab[HS][DS][WP];
    __shared__ unsigned long long wpk[CPB*27];

    const int tid = threadIdx.x;
    const int h0  = blockIdx.x * HT;
    const int d0  = blockIdx.y * DT;
    const int c0  = blockIdx.z * CPB;
    float* __restrict__ outbuf = blockIdx.z ? g_cost2 : g_cost;
    const int wg  = tid % 40;
    const int hl  = tid / 40;
    const int w0  = wg * 4;

    for (int i = tid; i < CPB*27; i += CONV_THREADS) {
        float k = __ldg(wgt + c0*27 + i);
        wpk[i] = pk2(k, k);
    }
    for (int i = tid; i < HS*DS; i += CONV_THREADS) {
        int shy = i / DS, sdd = i % DS;
        float* row = &slab[shy][sdd][0];
        row[0] = 0.f; row[1] = 0.f; row[2] = 0.f; row[3] = 0.f;
        row[164] = 0.f; row[165] = 0.f; row[166] = 0.f; row[167] = 0.f;
    }

    unsigned long long A[DT][2];
    #pragma unroll
    for (int od = 0; od < DT; od++) { A[od][0] = 0ull; A[od][1] = 0ull; }

    #pragma unroll 1
    for (int c = 0; c < CPB; c++) {
        __syncthreads();

        const float* __restrict__ vc = g_var + (size_t)(c0 + c) * DHWSZ;
        #pragma unroll
        for (int r = 0; r < 15; r++) {
            int idx = r*CONV_THREADS + tid;
            int row = idx / 40;
            int w4  = (idx % 40) * 4;
            int shy = row / DS;
            int sdd = row - shy*DS;
            int dd  = d0 - 1 + sdd;
            int hy  = h0 - 1 + shy;
            float4 v = make_float4(0.f, 0.f, 0.f, 0.f);
            if (dd >= 0 && dd < DDEP && hy >= 0 && hy < HH)
                v = *(const float4*)(vc + (size_t)dd*HWSZ + hy*WW + w4);
            *(float4*)&slab[shy][sdd][w4 + 4] = v;
        }
        __syncthreads();

        const unsigned long long* wc = wpk + c*27;
        #pragma unroll
        for (int dy = 0; dy < 3; dy++) {
            unsigned long long k00 = wc[(0*3+dy)*3+0], k01 = wc[(0*3+dy)*3+1], k02 = wc[(0*3+dy)*3+2];
            unsigned long long k10 = wc[(1*3+dy)*3+0], k11 = wc[(1*3+dy)*3+1], k12 = wc[(1*3+dy)*3+2];
            unsigned long long k20 = wc[(2*3+dy)*3+0], k21 = wc[(2*3+dy)*3+1], k22 = wc[(2*3+dy)*3+2];
            const float* hrow = &slab[hl + dy][0][0];
            #pragma unroll
            for (int sdd = 0; sdd < DS; sdd++) {
                const float* col = hrow + sdd*WP;
                float4 a = *(const float4*)(col + w0 + 4);
                float2 l = *(const float2*)(col + w0 + 2);
                float2 rr = *(const float2*)(col + w0 + 8);
                unsigned long long P0 = pk2(l.y,  a.x);
                unsigned long long P1 = pk2(a.x,  a.y);
                unsigned long long P2 = pk2(a.y,  a.z);
                unsigned long long P3 = pk2(a.z,  a.w);
                unsigned long long P4 = pk2(a.w,  rr.x);
                #pragma unroll
                for (int dz = 0; dz < 3; dz++) {
                    int od = sdd - dz;
                    if (od < 0 || od >= DT) continue;
                    unsigned long long q0 = (dz==0) ? k00 : (dz==1) ? k10 : k20;
                    unsigned long long q1 = (dz==0) ? k01 : (dz==1) ? k11 : k21;
                    unsigned long long q2 = (dz==0) ? k02 : (dz==1) ? k12 : k22;
                    A[od][0] = fma2(P0, q0, A[od][0]);
                    A[od][0] = fma2(P1, q1, A[od][0]);
                    A[od][0] = fma2(P2, q2, A[od][0]);
                    A[od][1] = fma2(P2, q0, A[od][1]);
                    A[od][1] = fma2(P3, q1, A[od][1]);
                    A[od][1] = fma2(P4, q2, A[od][1]);
                }
            }
        }
    }

    const int ob = (h0 + hl)*WW + w0;
    #pragma unroll
    for (int od = 0; od < DT; od++) {
        float o0, o1, o2, o3;
        upk2(A[od][0], o0, o1);
        upk2(A[od][1], o2, o3);
        float4 v = make_float4(o0, o1, o2, o3);
        *(float4*)(outbuf + (size_t)(d0 + od)*HWSZ + ob) = v;
    }
}

// ---------------- kernel 4: softmax / depth / confidence --------------------
__global__ void __launch_bounds__(256) k_post(const float* __restrict__ dv,
                                              float* __restrict__ out) {
    int pix = blockIdx.x * 256 + threadIdx.x;
    float p[DDEP];
    float mx = -1e30f;
    #pragma unroll
    for (int d = 0; d < DDEP; d++) {
        p[d] = g_cost[(size_t)d*HWSZ + pix] + g_cost2[(size_t)d*HWSZ + pix];
        mx = fmaxf(mx, p[d]);
    }
    float s = 0.0f;
    #pragma unroll
    for (int d = 0; d < DDEP; d++) { p[d] = expf(p[d] - mx); s += p[d]; }
    float inv = 1.0f / s;
    float depth = 0.0f, didx = 0.0f;
    #pragma unroll
    for (int d = 0; d < DDEP; d++) {
        float pr = p[d] * inv;
        p[d] = pr;
        depth += pr * __ldg(dv + d);
        didx  += pr * (float)d;
    }
    int di = (int)didx;
    di = min(max(di, 0), DDEP - 1);
    float conf = 0.0f;
    #pragma unroll
    for (int d = 0; d < DDEP; d++) {
        bool inwin = (d >= di - 1) && (d <= di + 2);
        conf += inwin ? p[d] : 0.0f;
    }
    out[pix]        = depth;
    out[HWSZ + pix] = conf;
}

// ---------------- launcher ---------------------------------------------------
extern "C" void kernel_launch(void* const* d_in, const int* in_sizes, int n_in,
                              void* d_out, int out_size) {
    const float* features = nullptr;
    const float* pm       = nullptr;
    const float* dv       = nullptr;
    const float* wgt      = nullptr;
    for (int i = 0; i < n_in; i++) {
        switch (in_sizes[i]) {
            case NV*CC*HWSZ: features = (const float*)d_in[i]; break;
            case 160:        pm       = (const float*)d_in[i]; break;
            case 48:         dv       = (const float*)d_in[i]; break;
            case 864:        wgt      = (const float*)d_in[i]; break;
            default: break;
        }
    }
    if (!features) features = (const float*)d_in[0];
    if (!pm)       pm       = (const float*)d_in[1];
    if (!dv)       dv       = (const float*)d_in[2];
    if (!wgt)      wgt      = (const float*)d_in[3];
    float* out = (float*)d_out;

    k_setup<<<1, 32>>>(pm);
    k_transpose<<<dim3(HWSZ/32, 1, NV), dim3(32, 32)>>>(features);
    k_var<<<HWSZ/TPX, VAR_THREADS>>>(dv);
    k_conv<<<dim3(HH/HT, DDEP/DT, CSPLIT), CONV_THREADS>>>(wgt);
    k_post<<<HWSZ/256, 256>>>(dv, out);
}

// round 6
// speedup vs baseline: 1.1854x; 1.1854x over previous
#include <cuda_runtime.h>

#define NV 5
#define NS 4
#define CC 32
#define HH 128
#define WW 160
#define DDEP 48
#define HWSZ (HH*WW)          // 20480
#define DHWSZ (DDEP*HWSZ)     // 983040

// conv tiling
#define HT 4
#define HS 6
#define DT 8
#define DS 10
#define WP 168
#define CONV_THREADS 160
#define CSPLIT 4
#define CPB (CC/CSPLIT)       // 8 channels per block

// ---------------- scratch ----------------------------------------------------
__device__ float g_rot[NS][9];
__device__ float g_trans[NS][3];
__device__ float g_feaT[NV*HWSZ*CC];            // (view, h, w, c)
__device__ float g_var[(size_t)CC*DHWSZ];       // planar (c, d,h,w)
__device__ float g_costp[CSPLIT][DHWSZ];        // partial costs

// ---------------- packed f32x2 helpers --------------------------------------
__device__ __forceinline__ unsigned long long pk2(float lo, float hi) {
    unsigned long long p;
    asm("mov.b64 %0, {%1, %2};" : "=l"(p) : "f"(lo), "f"(hi));
    return p;
}
__device__ __forceinline__ unsigned long long fma2(unsigned long long a,
                                                   unsigned long long b,
                                                   unsigned long long c) {
    unsigned long long d;
    asm("fma.rn.f32x2 %0, %1, %2, %3;" : "=l"(d) : "l"(a), "l"(b), "l"(c));
    return d;
}
__device__ __forceinline__ void upk2(unsigned long long p, float& lo, float& hi) {
    asm("mov.b64 {%0, %1}, %2;" : "=f"(lo), "=f"(hi) : "l"(p));
}

// ---------------- kernel 0: projection setup (1 thread, fp32) ---------------
__global__ void k_setup(const float* __restrict__ pm) {
    if (threadIdx.x != 0 || blockIdx.x != 0) return;
    float fused[NV][16];
    for (int n = 0; n < NV; n++) {
        const float* p0 = pm + n * 32;
        const float* p1 = p0 + 16;
        for (int i = 0; i < 16; i++) fused[n][i] = p0[i];
        for (int i = 0; i < 3; i++)
            for (int j = 0; j < 4; j++) {
                float s = 0.0f;
                for (int k = 0; k < 3; k++) s += p1[i*4+k] * p0[k*4+j];
                fused[n][i*4+j] = s;
            }
    }
    float a[4][8];
    for (int i = 0; i < 4; i++)
        for (int j = 0; j < 4; j++) {
            a[i][j]   = fused[0][i*4+j];
            a[i][j+4] = (i == j) ? 1.0f : 0.0f;
        }
    for (int col = 0; col < 4; col++) {
        int piv = col;
        for (int r = col + 1; r < 4; r++)
            if (fabsf(a[r][col]) > fabsf(a[piv][col])) piv = r;
        if (piv != col)
            for (int j = 0; j < 8; j++) { float t = a[col][j]; a[col][j] = a[piv][j]; a[piv][j] = t; }
        float d = a[col][col];
        for (int j = 0; j < 8; j++) a[col][j] /= d;
        for (int r = 0; r < 4; r++) {
            if (r == col) continue;
            float f = a[r][col];
            for (int j = 0; j < 8; j++) a[r][j] -= f * a[col][j];
        }
    }
    float inv[16];
    for (int i = 0; i < 4; i++)
        for (int j = 0; j < 4; j++) inv[i*4+j] = a[i][j+4];

    for (int v = 1; v < NV; v++) {
        float P[16];
        for (int i = 0; i < 4; i++)
            for (int j = 0; j < 4; j++) {
                float s = 0.0f;
                for (int k = 0; k < 4; k++) s += fused[v][i*4+k] * inv[k*4+j];
                P[i*4+j] = s;
            }
        for (int i = 0; i < 3; i++)
            for (int j = 0; j < 3; j++) g_rot[v-1][i*3+j] = P[i*4+j];
        for (int i = 0; i < 3; i++) g_trans[v-1][i] = P[i*4+3];
    }
}

// ---------------- kernel 1: transpose features (N,C,H,W) -> (N,HW,C) --------
__global__ void k_transpose(const float* __restrict__ f) {
    __shared__ float tile[32][33];
    int n  = blockIdx.z;
    int p0 = blockIdx.x * 32;
    int tx = threadIdx.x, ty = threadIdx.y;
    tile[ty][tx] = f[((size_t)(n*CC + ty))*HWSZ + p0 + tx];
    __syncthreads();
    g_feaT[((size_t)(n*HWSZ + p0 + ty))*CC + tx] = tile[tx][ty];
}

// ---------------- kernel 2: warp + variance (R4 version) --------------------
__global__ void __launch_bounds__(128) k_var(const float* __restrict__ dv) {
    __shared__ int4   s_idx[4][4][32];
    __shared__ float4 s_wt [4][4][32];
    __shared__ int    s_hw [4][32];
    __shared__ float  s_var[128*33];

    const int tid  = threadIdx.x;
    const int warp = tid >> 5;
    const int lane = tid & 31;
    const int gblock = blockIdx.x * 128;

    {
        int g  = gblock + tid;
        int d  = g / HWSZ;
        int hw = g - d * HWSZ;
        int h  = hw / WW;
        int w  = hw - h * WW;
        float fx = (float)w, fy = (float)h;
        float depth = __ldg(dv + d);
        #pragma unroll
        for (int v = 0; v < NS; v++) {
            float r0 = g_rot[v][0], r1 = g_rot[v][1], r2 = g_rot[v][2];
            float r3 = g_rot[v][3], r4 = g_rot[v][4], r5 = g_rot[v][5];
            float r6 = g_rot[v][6], r7 = g_rot[v][7], r8 = g_rot[v][8];
            float t0 = g_trans[v][0], t1 = g_trans[v][1], t2 = g_trans[v][2];
            float rx = r0*fx + r1*fy + r2;
            float ry = r3*fx + r4*fy + r5;
            float rz = r6*fx + r7*fy + r8;
            float X = rx*depth + t0;
            float Y = ry*depth + t1;
            float Z = rz*depth + t2;
            float px = X / Z;
            float py = Y / Z;
            float x0 = floorf(px), y0 = floorf(py);
            float x1 = x0 + 1.0f,  y1 = y0 + 1.0f;
            float wx1 = px - x0, wx0 = 1.0f - wx1;
            float wy1 = py - y0, wy0 = 1.0f - wy1;
            bool vx0 = (x0 >= 0.0f) && (x0 <= (float)(WW-1));
            bool vx1 = (x1 >= 0.0f) && (x1 <= (float)(WW-1));
            bool vy0 = (y0 >= 0.0f) && (y0 <= (float)(HH-1));
            bool vy1 = (y1 >= 0.0f) && (y1 <= (float)(HH-1));
            int cx0 = (int)fminf(fmaxf(x0, 0.0f), (float)(WW-1));
            int cx1 = (int)fminf(fmaxf(x1, 0.0f), (float)(WW-1));
            int cy0 = (int)fminf(fmaxf(y0, 0.0f), (float)(HH-1));
            int cy1 = (int)fminf(fmaxf(y1, 0.0f), (float)(HH-1));
            int4 id;
            id.x = cy0*WW + cx0;
            id.y = cy0*WW + cx1;
            id.z = cy1*WW + cx0;
            id.w = cy1*WW + cx1;
            float4 wt;
            wt.x = wx0*wy0 * ((vx0 && vy0) ? 1.0f : 0.0f);
            wt.y = wx1*wy0 * ((vx1 && vy0) ? 1.0f : 0.0f);
            wt.z = wx0*wy1 * ((vx0 && vy1) ? 1.0f : 0.0f);
            wt.w = wx1*wy1 * ((vx1 && vy1) ? 1.0f : 0.0f);
            s_idx[warp][v][lane] = id;
            s_wt [warp][v][lane] = wt;
        }
        s_hw[warp][lane] = hw;
    }
    __syncwarp();

    const int cg = lane & 7;
    const int q  = lane >> 3;
    const float4* fT = (const float4*)g_feaT;
    const float invN = 1.0f / (float)NV;

    #pragma unroll
    for (int it = 0; it < 8; it++) {
        int pt  = it*4 + q;
        int hw2 = s_hw[warp][pt];
        float4 ref = fT[hw2*8 + cg];
        float sx = ref.x, sy = ref.y, sz = ref.z, sw = ref.w;
        float qx = ref.x*ref.x, qy = ref.y*ref.y, qz = ref.z*ref.z, qw = ref.w*ref.w;
        #pragma unroll
        for (int v = 0; v < NS; v++) {
            int4   id = s_idx[warp][v][pt];
            float4 wt = s_wt [warp][v][pt];
            const float4* fv = fT + (size_t)(v+1)*HWSZ*8;
            float4 c00 = fv[id.x*8 + cg];
            float4 c01 = fv[id.y*8 + cg];
            float4 c10 = fv[id.z*8 + cg];
            float4 c11 = fv[id.w*8 + cg];
            float vx = wt.x*c00.x + wt.y*c01.x + wt.z*c10.x + wt.w*c11.x;
            float vy = wt.x*c00.y + wt.y*c01.y + wt.z*c10.y + wt.w*c11.y;
            float vz = wt.x*c00.z + wt.y*c01.z + wt.z*c10.z + wt.w*c11.z;
            float vw = wt.x*c00.w + wt.y*c01.w + wt.z*c10.w + wt.w*c11.w;
            sx += vx; sy += vy; sz += vz; sw += vw;
            qx += vx*vx; qy += vy*vy; qz += vz*vz; qw += vw*vw;
        }
        float mx = sx*invN, my = sy*invN, mz = sz*invN, mw = sw*invN;
        float vrx = qx*invN - mx*mx;
        float vry = qy*invN - my*my;
        float vrz = qz*invN - mz*mz;
        float vrw = qw*invN - mw*mw;
        int sbase = (warp*32 + pt)*33 + cg*4;
        s_var[sbase+0] = vrx;
        s_var[sbase+1] = vry;
        s_var[sbase+2] = vrz;
        s_var[sbase+3] = vrw;
    }
    __syncthreads();

    int gg = gblock + tid;
    #pragma unroll
    for (int c = 0; c < CC; c++)
        g_var[(size_t)c*DHWSZ + gg] = s_var[tid*33 + c];
}

// ---------------- kernel 3: 3x3x3 conv, 8 channels per block (4-way split) --
__global__ void __launch_bounds__(CONV_THREADS) k_conv(const float* __restrict__ wgt) {
    __shared__ float slab[HS][DS][WP];
    __shared__ unsigned long long wpk[CPB*27];

    const int tid = threadIdx.x;
    const int h0  = blockIdx.x * HT;
    const int d0  = blockIdx.y * DT;
    const int c0  = blockIdx.z * CPB;
    float* __restrict__ outbuf = g_costp[blockIdx.z];
    const int wg  = tid % 40;
    const int hl  = tid / 40;
    const int w0  = wg * 4;

    for (int i = tid; i < CPB*27; i += CONV_THREADS) {
        float k = __ldg(wgt + c0*27 + i);
        wpk[i] = pk2(k, k);
    }
    for (int i = tid; i < HS*DS; i += CONV_THREADS) {
        int shy = i / DS, sdd = i % DS;
        float* row = &slab[shy][sdd][0];
        row[0] = 0.f; row[1] = 0.f; row[2] = 0.f; row[3] = 0.f;
        row[164] = 0.f; row[165] = 0.f; row[166] = 0.f; row[167] = 0.f;
    }

    unsigned long long A[DT][2];
    #pragma unroll
    for (int od = 0; od < DT; od++) { A[od][0] = 0ull; A[od][1] = 0ull; }

    #pragma unroll 1
    for (int c = 0; c < CPB; c++) {
        __syncthreads();

        const float* __restrict__ vc = g_var + (size_t)(c0 + c) * DHWSZ;
        #pragma unroll
        for (int r = 0; r < 15; r++) {
            int idx = r*CONV_THREADS + tid;
            int row = idx / 40;
            int w4  = (idx % 40) * 4;
            int shy = row / DS;
            int sdd = row - shy*DS;
            int dd  = d0 - 1 + sdd;
            int hy  = h0 - 1 + shy;
            float4 v = make_float4(0.f, 0.f, 0.f, 0.f);
            if (dd >= 0 && dd < DDEP && hy >= 0 && hy < HH)
                v = *(const float4*)(vc + (size_t)dd*HWSZ + hy*WW + w4);
            *(float4*)&slab[shy][sdd][w4 + 4] = v;
        }
        __syncthreads();

        const unsigned long long* wc = wpk + c*27;
        #pragma unroll
        for (int dy = 0; dy < 3; dy++) {
            unsigned long long k00 = wc[(0*3+dy)*3+0], k01 = wc[(0*3+dy)*3+1], k02 = wc[(0*3+dy)*3+2];
            unsigned long long k10 = wc[(1*3+dy)*3+0], k11 = wc[(1*3+dy)*3+1], k12 = wc[(1*3+dy)*3+2];
            unsigned long long k20 = wc[(2*3+dy)*3+0], k21 = wc[(2*3+dy)*3+1], k22 = wc[(2*3+dy)*3+2];
            const float* hrow = &slab[hl + dy][0][0];
            #pragma unroll
            for (int sdd = 0; sdd < DS; sdd++) {
                const float* col = hrow + sdd*WP;
                float4 a = *(const float4*)(col + w0 + 4);
                float2 l = *(const float2*)(col + w0 + 2);
                float2 rr = *(const float2*)(col + w0 + 8);
                unsigned long long P0 = pk2(l.y,  a.x);
                unsigned long long P1 = pk2(a.x,  a.y);
                unsigned long long P2 = pk2(a.y,  a.z);
                unsigned long long P3 = pk2(a.z,  a.w);
                unsigned long long P4 = pk2(a.w,  rr.x);
                #pragma unroll
                for (int dz = 0; dz < 3; dz++) {
                    int od = sdd - dz;
                    if (od < 0 || od >= DT) continue;
                    unsigned long long q0 = (dz==0) ? k00 : (dz==1) ? k10 : k20;
                    unsigned long long q1 = (dz==0) ? k01 : (dz==1) ? k11 : k21;
                    unsigned long long q2 = (dz==0) ? k02 : (dz==1) ? k12 : k22;
                    A[od][0] = fma2(P0, q0, A[od][0]);
                    A[od][0] = fma2(P1, q1, A[od][0]);
                    A[od][0] = fma2(P2, q2, A[od][0]);
                    A[od][1] = fma2(P2, q0, A[od][1]);
                    A[od][1] = fma2(P3, q1, A[od][1]);
                    A[od][1] = fma2(P4, q2, A[od][1]);
                }
            }
        }
    }

    const int ob = (h0 + hl)*WW + w0;
    #pragma unroll
    for (int od = 0; od < DT; od++) {
        float o0, o1, o2, o3;
        upk2(A[od][0], o0, o1);
        upk2(A[od][1], o2, o3);
        float4 v = make_float4(o0, o1, o2, o3);
        *(float4*)(outbuf + (size_t)(d0 + od)*HWSZ + ob) = v;
    }
}

// ---------------- kernel 4: softmax / depth / confidence --------------------
__global__ void __launch_bounds__(128) k_post(const float* __restrict__ dv,
                                              float* __restrict__ out) {
    int pix = blockIdx.x * 128 + threadIdx.x;
    float p[DDEP];
    float mx = -1e30f;
    #pragma unroll
    for (int d = 0; d < DDEP; d++) {
        size_t o = (size_t)d*HWSZ + pix;
        p[d] = (g_costp[0][o] + g_costp[1][o]) + (g_costp[2][o] + g_costp[3][o]);
        mx = fmaxf(mx, p[d]);
    }
    float s = 0.0f;
    #pragma unroll
    for (int d = 0; d < DDEP; d++) { p[d] = expf(p[d] - mx); s += p[d]; }
    float inv = 1.0f / s;
    float depth = 0.0f, didx = 0.0f;
    #pragma unroll
    for (int d = 0; d < DDEP; d++) {
        float pr = p[d] * inv;
        p[d] = pr;
        depth += pr * __ldg(dv + d);
        didx  += pr * (float)d;
    }
    int di = (int)didx;
    di = min(max(di, 0), DDEP - 1);
    float conf = 0.0f;
    #pragma unroll
    for (int d = 0; d < DDEP; d++) {
        bool inwin = (d >= di - 1) && (d <= di + 2);
        conf += inwin ? p[d] : 0.0f;
    }
    out[pix]        = depth;
    out[HWSZ + pix] = conf;
}

// ---------------- launcher ---------------------------------------------------
extern "C" void kernel_launch(void* const* d_in, const int* in_sizes, int n_in,
                              void* d_out, int out_size) {
    const float* features = nullptr;
    const float* pm       = nullptr;
    const float* dv       = nullptr;
    const float* wgt      = nullptr;
    for (int i = 0; i < n_in; i++) {
        switch (in_sizes[i]) {
            case NV*CC*HWSZ: features = (const float*)d_in[i]; break;
            case 160:        pm       = (const float*)d_in[i]; break;
            case 48:         dv       = (const float*)d_in[i]; break;
            case 864:        wgt      = (const float*)d_in[i]; break;
            default: break;
        }
    }
    if (!features) features = (const float*)d_in[0];
    if (!pm)       pm       = (const float*)d_in[1];
    if (!dv)       dv       = (const float*)d_in[2];
    if (!wgt)      wgt      = (const float*)d_in[3];
    float* out = (float*)d_out;

    k_setup<<<1, 32>>>(pm);
    k_transpose<<<dim3(HWSZ/32, 1, NV), dim3(32, 32)>>>(features);
    k_var<<<DHWSZ/128, 128>>>(dv);
    k_conv<<<dim3(HH/HT, DDEP/DT, CSPLIT), CONV_THREADS>>>(wgt);
    k_post<<<HWSZ/128, 128>>>(dv, out);
}